// round 15
// baseline (speedup 1.0000x reference)
#include <cuda_runtime.h>
#include <cuda_fp16.h>
#include <math_constants.h>

// SparseSelfAttention: B=2,H=16,L=2048,D=64,BLK=32,NB=64 (causal band, window=8)
// Flash attention: QK^T tf32 mma (m16n8k8), PV fp16 mma (m16n8k16), register-direct P.
// CTA = 256 threads = 8 warps = 128 q rows (4 q-blocks) -> KV staging amortized
// over the causal-band union (~11 blocks per CTA instead of 2x9).

#define HEADS 16
#define SEQ   2048
#define DIM   64
#define NB    64
#define BLK   32

#define NSTR  72    // Ks row stride (u32); conflict-free frag reads
#define VPSTR 72    // Vpair row stride (u32)
#define QSTR  68
#define LOG2E 1.4426950408889634f

__device__ __forceinline__ unsigned f2tf32(float f) {
    unsigned r;
    asm("cvt.rna.tf32.f32 %0, %1;" : "=r"(r) : "f"(f));
    return r;
}

__device__ __forceinline__ float ex2(float x) {
    float r;
    asm("ex2.approx.ftz.f32 %0, %1;" : "=f"(r) : "f"(x));
    return r;
}

__device__ __forceinline__ unsigned packh2(float lo, float hi) {
    __half2 h;
    h.x = __float2half_rn(lo);
    h.y = __float2half_rn(hi);
    return *reinterpret_cast<unsigned*>(&h);
}

__device__ __forceinline__ void mma_tf32(float c[4], const unsigned a[4], const unsigned b[2]) {
    asm volatile("mma.sync.aligned.m16n8k8.row.col.f32.tf32.tf32.f32 "
                 "{%0,%1,%2,%3}, {%4,%5,%6,%7}, {%8,%9}, {%0,%1,%2,%3};"
                 : "+f"(c[0]), "+f"(c[1]), "+f"(c[2]), "+f"(c[3])
                 : "r"(a[0]), "r"(a[1]), "r"(a[2]), "r"(a[3]),
                   "r"(b[0]), "r"(b[1]));
}

__device__ __forceinline__ void mma_f16(float c[4], const unsigned a[4], const unsigned b[2]) {
    asm volatile("mma.sync.aligned.m16n8k16.row.col.f32.f16.f16.f32 "
                 "{%0,%1,%2,%3}, {%4,%5,%6,%7}, {%8,%9}, {%0,%1,%2,%3};"
                 : "+f"(c[0]), "+f"(c[1]), "+f"(c[2]), "+f"(c[3])
                 : "r"(a[0]), "r"(a[1]), "r"(a[2]), "r"(a[3]),
                   "r"(b[0]), "r"(b[1]));
}

__global__ __launch_bounds__(256, 2)
void sparse_attn_tc(const float* __restrict__ qg,
                    const float* __restrict__ kg,
                    const float* __restrict__ vg,
                    const float* __restrict__ kpm,
                    const int*   __restrict__ layout,
                    float* __restrict__ outg)
{
    __shared__ __align__(16) union {
        struct {
            unsigned Ks[BLK * NSTR];      // tf32 [kv row][dim]
            unsigned Vp[16 * VPSTR];      // half2 pairs [kv pair][dim]
        } kv;
        unsigned qstage[128 * QSTR];      // 34816 B
    } sm;
    __shared__ float kpms[BLK];
    __shared__ int lay[4 * NB];           // 4 layout rows
    __shared__ int uni[NB];

    const int tid  = threadIdx.x;         // 0..255
    const int w    = tid >> 5;            // 0..7
    const int lane = tid & 31;
    const int gid  = lane >> 2;
    const int t4   = lane & 3;

    const int i0 = blockIdx.x;            // q rows [i0*128, i0*128+128)
    const int h  = blockIdx.y;
    const int b  = blockIdx.z;

    const size_t bh = (size_t)b * HEADS + h;
    const float* kbase = kg + bh * SEQ * DIM;
    const float* vbase = vg + bh * SEQ * DIM;

    // 4 layout rows (256 threads -> 256 ints exactly)
    lay[tid] = layout[((size_t)h * NB + (i0 * 4 + (tid >> 6))) * NB + (tid & 63)];

    // ---- stage Q (tf32, scaled by 0.125*log2e) ----
    const float* qptr = qg + (bh * SEQ + (size_t)i0 * 128) * DIM;
    #pragma unroll
    for (int jj = 0; jj < 8; jj++) {
        int idx = tid + 256 * jj;         // 2048 float4
        int row = idx >> 4, d4 = idx & 15;
        float4 qv = reinterpret_cast<const float4*>(qptr)[idx];
        const float qs = 0.125f * LOG2E;
        uint4 t;
        t.x = f2tf32(qv.x * qs); t.y = f2tf32(qv.y * qs);
        t.z = f2tf32(qv.z * qs); t.w = f2tf32(qv.w * qs);
        *reinterpret_cast<uint4*>(&sm.qstage[row * QSTR + d4 * 4]) = t;
    }
    __syncthreads();

    if (tid < NB) uni[tid] = lay[tid] | lay[64 + tid] | lay[128 + tid] | lay[192 + tid];

    // ---- Q A-fragments resident for whole kernel ----
    const int lrow = w * 16 + gid;        // 0..127
    unsigned qa[8][4];
    #pragma unroll
    for (int kst = 0; kst < 8; kst++) {
        qa[kst][0] = sm.qstage[ lrow      * QSTR + kst * 8 + t4    ];
        qa[kst][1] = sm.qstage[(lrow + 8) * QSTR + kst * 8 + t4    ];
        qa[kst][2] = sm.qstage[ lrow      * QSTR + kst * 8 + t4 + 4];
        qa[kst][3] = sm.qstage[(lrow + 8) * QSTR + kst * 8 + t4 + 4];
    }
    __syncthreads();   // qstage dead; kv live; uni visible

    const int* layw = &lay[(w >> 1) * NB];   // this warp's q-block layout row

    float lsum_lo = 0.f, lsum_hi = 0.f;
    float o[8][4];
    #pragma unroll
    for (int n = 0; n < 8; n++) { o[n][0]=0.f; o[n][1]=0.f; o[n][2]=0.f; o[n][3]=0.f; }

    for (int j = 0; j < NB; j++) {
        if (!uni[j]) continue;

        const float* kp = kbase + (size_t)j * BLK * DIM;
        const float* vp = vbase + (size_t)j * BLK * DIM;

        // ---- stage K as tf32 (512 float4 over 256 threads) ----
        #pragma unroll
        for (int jj = 0; jj < 2; jj++) {
            int ii = tid + 256 * jj;
            int row = ii >> 4, c4 = ii & 15;
            float4 kv4 = reinterpret_cast<const float4*>(kp)[ii];
            uint4 tk;
            tk.x = f2tf32(kv4.x); tk.y = f2tf32(kv4.y);
            tk.z = f2tf32(kv4.z); tk.w = f2tf32(kv4.w);
            *reinterpret_cast<uint4*>(&sm.kv.Ks[row * NSTR + c4 * 4]) = tk;
        }

        // ---- stage V as half2 row-pairs: Vp[p][d] = {V[2p][d], V[2p+1][d]} ----
        #pragma unroll
        for (int jj = 0; jj < 2; jj++) {
            int ii = tid + 256 * jj;          // 512 tasks: (pair p, dim-pair d2)
            int p = ii >> 5, d2 = ii & 31;
            float2 ve = *reinterpret_cast<const float2*>(vp + (2 * p    ) * DIM + 2 * d2);
            float2 vo = *reinterpret_cast<const float2*>(vp + (2 * p + 1) * DIM + 2 * d2);
            uint2 wds;
            wds.x = packh2(ve.x, vo.x);
            wds.y = packh2(ve.y, vo.y);
            *reinterpret_cast<uint2*>(&sm.kv.Vp[p * VPSTR + 2 * d2]) = wds;
        }
        if (tid < BLK) kpms[tid] = kpm[(size_t)b * SEQ + j * BLK + tid] * LOG2E;
        __syncthreads();

        if (layw[j]) {
            // ---- phase 1: QK^T, 4 independent n-tile chains ----
            float c[4][4];
            #pragma unroll
            for (int g = 0; g < 4; g++) {
                float2 kb = *reinterpret_cast<const float2*>(&kpms[g * 8 + 2 * t4]);
                c[g][0] = kb.x; c[g][1] = kb.y; c[g][2] = kb.x; c[g][3] = kb.y;
            }
            #pragma unroll
            for (int kst = 0; kst < 8; kst++) {
                #pragma unroll
                for (int g = 0; g < 4; g++) {
                    unsigned bb[2];
                    bb[0] = sm.kv.Ks[(g * 8 + gid) * NSTR + kst * 8 + t4    ];
                    bb[1] = sm.kv.Ks[(g * 8 + gid) * NSTR + kst * 8 + t4 + 4];
                    mma_tf32(c[g], qa[kst], bb);
                }
            }

            // ---- phase 2: softmax (no max) + pack P as fp16 A-fragments ----
            unsigned pa[4][2];
            #pragma unroll
            for (int g = 0; g < 4; g++) {
                float p0 = ex2(c[g][0]);
                float p1 = ex2(c[g][1]);
                float p2 = ex2(c[g][2]);
                float p3 = ex2(c[g][3]);
                lsum_lo += p0 + p1;
                lsum_hi += p2 + p3;
                pa[g][0] = packh2(p0, p1);
                pa[g][1] = packh2(p2, p3);
            }

            // ---- phase 3: PV fp16 m16n8k16 ----
            #pragma unroll
            for (int nt2 = 0; nt2 < 8; nt2++) {
                #pragma unroll
                for (int kst = 0; kst < 2; kst++) {
                    unsigned aa[4];
                    aa[0] = pa[2 * kst    ][0];
                    aa[1] = pa[2 * kst    ][1];
                    aa[2] = pa[2 * kst + 1][0];
                    aa[3] = pa[2 * kst + 1][1];
                    unsigned bb[2];
                    bb[0] = sm.kv.Vp[(8 * kst + t4    ) * VPSTR + nt2 * 8 + gid];
                    bb[1] = sm.kv.Vp[(8 * kst + 4 + t4) * VPSTR + nt2 * 8 + gid];
                    mma_f16(o[nt2], aa, bb);
                }
            }
        }
        __syncthreads();
    }

    // ---- epilogue: quad reduction of l, normalize, store ----
    #pragma unroll
    for (int off = 1; off < 4; off <<= 1) {
        lsum_lo += __shfl_xor_sync(0xffffffffu, lsum_lo, off);
        lsum_hi += __shfl_xor_sync(0xffffffffu, lsum_hi, off);
    }
    float inv_lo = 1.0f / lsum_lo;
    float inv_hi = 1.0f / lsum_hi;
    float* op = outg + (bh * SEQ + (size_t)i0 * 128) * DIM;
    #pragma unroll
    for (int nt2 = 0; nt2 < 8; nt2++) {
        float2 vlo, vhi;
        vlo.x = o[nt2][0] * inv_lo; vlo.y = o[nt2][1] * inv_lo;
        vhi.x = o[nt2][2] * inv_hi; vhi.y = o[nt2][3] * inv_hi;
        reinterpret_cast<float2*>(op +  lrow      * DIM)[nt2 * 4 + t4] = vlo;
        reinterpret_cast<float2*>(op + (lrow + 8) * DIM)[nt2 * 4 + t4] = vhi;
    }
}

extern "C" void kernel_launch(void* const* d_in, const int* in_sizes, int n_in,
                              void* d_out, int out_size)
{
    const float* q   = (const float*)d_in[0];
    const float* k   = (const float*)d_in[1];
    const float* v   = (const float*)d_in[2];
    const float* kpm = (const float*)d_in[3];
    const int* layout = (const int*)d_in[4];
    float* out = (float*)d_out;

    dim3 grid(SEQ / 128, HEADS, 2);   // 16 x 16 x 2 = 512 CTAs
    dim3 block(256);
    sparse_attn_tc<<<grid, block>>>(q, k, v, kpm, layout, out);
}

// round 16
// speedup vs baseline: 1.0424x; 1.0424x over previous
#include <cuda_runtime.h>
#include <cuda_fp16.h>
#include <math_constants.h>

// SparseSelfAttention: B=2,H=16,L=2048,D=64,BLK=32,NB=64 (causal band, window=8)
// Flash attention: QK^T tf32 mma (K fed as raw fp32 = RZ tf32), PV fp16 mma with
// register-direct P. CTA = 256 thr = 128 q rows (4 q-blocks). Double-buffered
// staging: K/kpm via cp.async, V via register prefetch + packed STS.

#define HEADS 16
#define SEQ   2048
#define DIM   64
#define NB    64
#define BLK   32

#define NSTR  72    // K row stride (u32); conflict-free frag reads
#define VPSTR 72    // Vpair row stride (u32)
#define QSTR  68
#define LOG2E 1.4426950408889634f

__device__ __forceinline__ unsigned f2tf32(float f) {
    unsigned r;
    asm("cvt.rna.tf32.f32 %0, %1;" : "=r"(r) : "f"(f));
    return r;
}

__device__ __forceinline__ float ex2(float x) {
    float r;
    asm("ex2.approx.ftz.f32 %0, %1;" : "=f"(r) : "f"(x));
    return r;
}

__device__ __forceinline__ unsigned packh2(float lo, float hi) {
    __half2 h;
    h.x = __float2half_rn(lo);
    h.y = __float2half_rn(hi);
    return *reinterpret_cast<unsigned*>(&h);
}

__device__ __forceinline__ void mma_tf32(float c[4], const unsigned a[4], const unsigned b[2]) {
    asm volatile("mma.sync.aligned.m16n8k8.row.col.f32.tf32.tf32.f32 "
                 "{%0,%1,%2,%3}, {%4,%5,%6,%7}, {%8,%9}, {%0,%1,%2,%3};"
                 : "+f"(c[0]), "+f"(c[1]), "+f"(c[2]), "+f"(c[3])
                 : "r"(a[0]), "r"(a[1]), "r"(a[2]), "r"(a[3]),
                   "r"(b[0]), "r"(b[1]));
}

__device__ __forceinline__ void mma_f16(float c[4], const unsigned a[4], const unsigned b[2]) {
    asm volatile("mma.sync.aligned.m16n8k16.row.col.f32.f16.f16.f32 "
                 "{%0,%1,%2,%3}, {%4,%5,%6,%7}, {%8,%9}, {%0,%1,%2,%3};"
                 : "+f"(c[0]), "+f"(c[1]), "+f"(c[2]), "+f"(c[3])
                 : "r"(a[0]), "r"(a[1]), "r"(a[2]), "r"(a[3]),
                   "r"(b[0]), "r"(b[1]));
}

__device__ __forceinline__ unsigned smem_u32(const void* p) {
    unsigned a;
    asm("{ .reg .u64 t; cvta.to.shared.u64 t, %1; cvt.u32.u64 %0, t; }" : "=r"(a) : "l"(p));
    return a;
}

__device__ __forceinline__ void cp16(unsigned dst, const void* src) {
    asm volatile("cp.async.ca.shared.global [%0], [%1], 16;\n" :: "r"(dst), "l"(src));
}

__global__ __launch_bounds__(256, 2)
void sparse_attn_tc(const float* __restrict__ qg,
                    const float* __restrict__ kg,
                    const float* __restrict__ vg,
                    const float* __restrict__ kpm,
                    const int*   __restrict__ layout,
                    float* __restrict__ outg)
{
    __shared__ __align__(16) union {
        struct {
            float    Kr[2][BLK * NSTR];    // raw fp32 K (RZ tf32 at use), 2 stages
            unsigned Vp[2][16 * VPSTR];    // packed half2 V pairs, 2 stages
            float    kp2[2][BLK];          // raw kpm, 2 stages
        } st;
        unsigned qstage[128 * QSTR];
    } sm;
    __shared__ int lay[4 * NB];
    __shared__ int jlist[NB];
    __shared__ int jcnt;

    const int tid  = threadIdx.x;          // 0..255
    const int w    = tid >> 5;             // 0..7
    const int lane = tid & 31;
    const int gid  = lane >> 2;
    const int t4   = lane & 3;

    const int i0 = blockIdx.x;             // q rows [i0*128, i0*128+128)
    const int h  = blockIdx.y;
    const int b  = blockIdx.z;

    const size_t bh = (size_t)b * HEADS + h;
    const float* kbase = kg + bh * SEQ * DIM;
    const float* vbase = vg + bh * SEQ * DIM;

    lay[tid] = layout[((size_t)h * NB + (i0 * 4 + (tid >> 6))) * NB + (tid & 63)];

    // ---- stage Q (tf32 RNA, scaled by 0.125*log2e) ----
    const float* qptr = qg + (bh * SEQ + (size_t)i0 * 128) * DIM;
    #pragma unroll
    for (int jj = 0; jj < 8; jj++) {
        int idx = tid + 256 * jj;
        int row = idx >> 4, d4 = idx & 15;
        float4 qv = reinterpret_cast<const float4*>(qptr)[idx];
        const float qs = 0.125f * LOG2E;
        uint4 t;
        t.x = f2tf32(qv.x * qs); t.y = f2tf32(qv.y * qs);
        t.z = f2tf32(qv.z * qs); t.w = f2tf32(qv.w * qs);
        *reinterpret_cast<uint4*>(&sm.qstage[row * QSTR + d4 * 4]) = t;
    }
    __syncthreads();

    if (tid == 0) {
        int c = 0;
        for (int j = 0; j < NB; j++)
            if (lay[j] | lay[64 + j] | lay[128 + j] | lay[192 + j]) jlist[c++] = j;
        jcnt = c;
    }

    // ---- Q A-fragments resident ----
    const int lrow = w * 16 + gid;
    unsigned qa[8][4];
    #pragma unroll
    for (int kst = 0; kst < 8; kst++) {
        qa[kst][0] = sm.qstage[ lrow      * QSTR + kst * 8 + t4    ];
        qa[kst][1] = sm.qstage[(lrow + 8) * QSTR + kst * 8 + t4    ];
        qa[kst][2] = sm.qstage[ lrow      * QSTR + kst * 8 + t4 + 4];
        qa[kst][3] = sm.qstage[(lrow + 8) * QSTR + kst * 8 + t4 + 4];
    }
    __syncthreads();   // qstage dead; stages live; jlist visible

    const int nj = jcnt;
    const int* layw = &lay[(w >> 1) * NB];
    const unsigned kr_base = smem_u32(&sm.st.Kr[0][0]);
    const unsigned kp_base = smem_u32(&sm.st.kp2[0][0]);
    const int krow = tid >> 4, kc4 = tid & 15;   // K cp.async coords (task tid, tid+256)

    // V prefetch task coords (2 tasks per thread)
    const int vp0 = tid >> 5,        vd0 = tid & 31;
    const int vp1 = (tid + 256) >> 5, vd1 = (tid + 256) & 31;

    // ---- prologue: fully stage block jlist[0] into stage 0 ----
    {
        const int j0 = jlist[0];
        const float* kp = kbase + (size_t)j0 * BLK * DIM;
        const float* vp = vbase + (size_t)j0 * BLK * DIM;
        cp16(kr_base + (unsigned)((krow * NSTR + kc4 * 4) * 4), kp + krow * DIM + kc4 * 4);
        cp16(kr_base + (unsigned)(((krow + 16) * NSTR + kc4 * 4) * 4), kp + (krow + 16) * DIM + kc4 * 4);
        if (tid < 8) cp16(kp_base + tid * 16, kpm + (size_t)b * SEQ + j0 * BLK + tid * 4);
        // V: LDG -> pack -> STS
        float2 ve0 = *reinterpret_cast<const float2*>(vp + (2 * vp0    ) * DIM + 2 * vd0);
        float2 vo0 = *reinterpret_cast<const float2*>(vp + (2 * vp0 + 1) * DIM + 2 * vd0);
        float2 ve1 = *reinterpret_cast<const float2*>(vp + (2 * vp1    ) * DIM + 2 * vd1);
        float2 vo1 = *reinterpret_cast<const float2*>(vp + (2 * vp1 + 1) * DIM + 2 * vd1);
        uint2 w0, w1;
        w0.x = packh2(ve0.x, vo0.x); w0.y = packh2(ve0.y, vo0.y);
        w1.x = packh2(ve1.x, vo1.x); w1.y = packh2(ve1.y, vo1.y);
        *reinterpret_cast<uint2*>(&sm.st.Vp[0][vp0 * VPSTR + 2 * vd0]) = w0;
        *reinterpret_cast<uint2*>(&sm.st.Vp[0][vp1 * VPSTR + 2 * vd1]) = w1;
        asm volatile("cp.async.commit_group;\n" ::);
        asm volatile("cp.async.wait_group 0;\n" ::);
    }
    __syncthreads();

    float lsum_lo = 0.f, lsum_hi = 0.f;
    float o[8][4];
    #pragma unroll
    for (int n = 0; n < 8; n++) { o[n][0]=0.f; o[n][1]=0.f; o[n][2]=0.f; o[n][3]=0.f; }

    for (int idx = 0; idx < nj; idx++) {
        const int s = idx & 1;
        const int j = jlist[idx];
        const int havenext = (idx + 1 < nj);

        // ---- prefetch next: K/kpm via cp.async, V via LDG into registers ----
        uint2 w0, w1;
        if (havenext) {
            const int jn = jlist[idx + 1];
            const float* kp = kbase + (size_t)jn * BLK * DIM;
            const float* vp = vbase + (size_t)jn * BLK * DIM;
            const unsigned so = (unsigned)((s ^ 1) * BLK * NSTR * 4);
            cp16(kr_base + so + (unsigned)((krow * NSTR + kc4 * 4) * 4), kp + krow * DIM + kc4 * 4);
            cp16(kr_base + so + (unsigned)(((krow + 16) * NSTR + kc4 * 4) * 4), kp + (krow + 16) * DIM + kc4 * 4);
            if (tid < 8) cp16(kp_base + (unsigned)((s ^ 1) * BLK * 4) + tid * 16,
                              kpm + (size_t)b * SEQ + jn * BLK + tid * 4);
            float2 ve0 = *reinterpret_cast<const float2*>(vp + (2 * vp0    ) * DIM + 2 * vd0);
            float2 vo0 = *reinterpret_cast<const float2*>(vp + (2 * vp0 + 1) * DIM + 2 * vd0);
            float2 ve1 = *reinterpret_cast<const float2*>(vp + (2 * vp1    ) * DIM + 2 * vd1);
            float2 vo1 = *reinterpret_cast<const float2*>(vp + (2 * vp1 + 1) * DIM + 2 * vd1);
            w0.x = packh2(ve0.x, vo0.x); w0.y = packh2(ve0.y, vo0.y);
            w1.x = packh2(ve1.x, vo1.x); w1.y = packh2(ve1.y, vo1.y);
        }
        asm volatile("cp.async.commit_group;\n" ::);

        if (layw[j]) {
            const unsigned* Kw = reinterpret_cast<const unsigned*>(&sm.st.Kr[s][0]);
            const float* kpv = &sm.st.kp2[s][0];
            const unsigned* Vw = &sm.st.Vp[s][0];

            // ---- phase 1: QK^T, 4 independent n-tile chains ----
            float c[4][4];
            #pragma unroll
            for (int g = 0; g < 4; g++) {
                float2 kb = *reinterpret_cast<const float2*>(&kpv[g * 8 + 2 * t4]);
                c[g][0] = kb.x * LOG2E; c[g][1] = kb.y * LOG2E;
                c[g][2] = c[g][0];      c[g][3] = c[g][1];
            }
            #pragma unroll
            for (int kst = 0; kst < 8; kst++) {
                #pragma unroll
                for (int g = 0; g < 4; g++) {
                    unsigned bb[2];
                    bb[0] = Kw[(g * 8 + gid) * NSTR + kst * 8 + t4    ];
                    bb[1] = Kw[(g * 8 + gid) * NSTR + kst * 8 + t4 + 4];
                    mma_tf32(c[g], qa[kst], bb);
                }
            }

            // ---- phase 2: softmax (no max) + pack P fp16 ----
            unsigned pa[4][2];
            #pragma unroll
            for (int g = 0; g < 4; g++) {
                float p0 = ex2(c[g][0]);
                float p1 = ex2(c[g][1]);
                float p2 = ex2(c[g][2]);
                float p3 = ex2(c[g][3]);
                lsum_lo += p0 + p1;
                lsum_hi += p2 + p3;
                pa[g][0] = packh2(p0, p1);
                pa[g][1] = packh2(p2, p3);
            }

            // ---- phase 3: PV fp16 m16n8k16 ----
            #pragma unroll
            for (int nt2 = 0; nt2 < 8; nt2++) {
                #pragma unroll
                for (int kst = 0; kst < 2; kst++) {
                    unsigned aa[4];
                    aa[0] = pa[2 * kst    ][0];
                    aa[1] = pa[2 * kst    ][1];
                    aa[2] = pa[2 * kst + 1][0];
                    aa[3] = pa[2 * kst + 1][1];
                    unsigned bb[2];
                    bb[0] = Vw[(8 * kst + t4    ) * VPSTR + nt2 * 8 + gid];
                    bb[1] = Vw[(8 * kst + 4 + t4) * VPSTR + nt2 * 8 + gid];
                    mma_f16(o[nt2], aa, bb);
                }
            }
        }

        // ---- land prefetched V into the other stage ----
        if (havenext) {
            *reinterpret_cast<uint2*>(&sm.st.Vp[s ^ 1][vp0 * VPSTR + 2 * vd0]) = w0;
            *reinterpret_cast<uint2*>(&sm.st.Vp[s ^ 1][vp1 * VPSTR + 2 * vd1]) = w1;
        }
        asm volatile("cp.async.wait_group 0;\n" ::);
        __syncthreads();
    }

    // ---- epilogue: quad reduction of l, normalize, store ----
    #pragma unroll
    for (int off = 1; off < 4; off <<= 1) {
        lsum_lo += __shfl_xor_sync(0xffffffffu, lsum_lo, off);
        lsum_hi += __shfl_xor_sync(0xffffffffu, lsum_hi, off);
    }
    float inv_lo = 1.0f / lsum_lo;
    float inv_hi = 1.0f / lsum_hi;
    float* op = outg + (bh * SEQ + (size_t)i0 * 128) * DIM;
    #pragma unroll
    for (int nt2 = 0; nt2 < 8; nt2++) {
        float2 vlo, vhi;
        vlo.x = o[nt2][0] * inv_lo; vlo.y = o[nt2][1] * inv_lo;
        vhi.x = o[nt2][2] * inv_hi; vhi.y = o[nt2][3] * inv_hi;
        reinterpret_cast<float2*>(op +  lrow      * DIM)[nt2 * 4 + t4] = vlo;
        reinterpret_cast<float2*>(op + (lrow + 8) * DIM)[nt2 * 4 + t4] = vhi;
    }
}

extern "C" void kernel_launch(void* const* d_in, const int* in_sizes, int n_in,
                              void* d_out, int out_size)
{
    const float* q   = (const float*)d_in[0];
    const float* k   = (const float*)d_in[1];
    const float* v   = (const float*)d_in[2];
    const float* kpm = (const float*)d_in[3];
    const int* layout = (const int*)d_in[4];
    float* out = (float*)d_out;

    dim3 grid(SEQ / 128, HEADS, 2);
    dim3 block(256);
    sparse_attn_tc<<<grid, block>>>(q, k, v, kpm, layout, out);
}